// round 12
// baseline (speedup 1.0000x reference)
#include <cuda_runtime.h>
#include <cuda_bf16.h>

// out[b, 1+d, p] = x[b, c, hx(p)*16+pi, hy(p)*16+pj] + pos[1+d, p]
//   where d = c*256 + pi*16 + pj, (hx,hy) = hilbert_d2xy(32, p)
// out[b, 0, e]   = cls[e] + pos[0, e]   (fused into ptile==0,dtile==0 CTA)
//
// Final form: smem-free 4x4 register transpose (best of 7 variants; all
// converge at the ~6.25 TB/s memory-system wall for this 50/50 streaming
// read/write mix). 8-lane groups read full 64B patch rows (full sectors,
// MLP-4 batched); 4 pos loads (L2-resident) batched before stores; every
// STG.128 writes a full 128B output line. This round: plain write-back
// stores (drop .cs) — last untested cache-op knob.

__global__ __launch_bounds__(256) void hilbert_main_kernel(
    const float* __restrict__ x,
    const float* __restrict__ cls,
    const float* __restrict__ pos,
    float* __restrict__ out)
{
    const int tid = threadIdx.x;
    const int w   = tid >> 5;          // warp 0..7  -> d-quads 4w..4w+3
    const int l   = tid & 31;

    const int ptile = blockIdx.x;      // 0..31
    const int dtile = blockIdx.y;      // 0..7
    const int b     = blockIdx.z;      // 0..63

    const int c   = dtile >> 1;        // channel
    const int pi0 = (dtile & 1) * 8;   // starting patch row within channel
    const int p0  = ptile * 32;
    const int d0  = dtile * 128;
    const int out_b = b * (1025 * 1024);

    // Per-lane Hilbert d2xy for patch p0+l (N=32, 5 iterations)
    int pb;
    {
        int t = p0 + l;
        int hx = 0, hy = 0;
        #pragma unroll
        for (int s = 1; s < 32; s <<= 1) {
            int rx = 1 & (t >> 1);
            int ry = 1 & (t ^ rx);
            if (ry == 0) {
                if (rx == 1) { hx = s - 1 - hx; hy = s - 1 - hy; }
                int tmp = hx; hx = hy; hy = tmp;
            }
            hx += s * rx;
            hy += s * ry;
            t >>= 2;
        }
        pb = ((b * 4 + c) * 512 + hx * 16 + pi0) * 512 + hy * 16;
    }

    // Fused row0: out[b, 0, :] = cls + pos[0, :]  (one CTA per batch)
    if (ptile == 0 && dtile == 0) {
        float4 cv = *reinterpret_cast<const float4*>(cls + tid * 4);
        float4 pv = *reinterpret_cast<const float4*>(pos + tid * 4);
        cv.x += pv.x; cv.y += pv.y; cv.z += pv.z; cv.w += pv.w;
        *reinterpret_cast<float4*>(out + out_b + tid * 4) = cv;
    }

    const int q = l & 7;               // p-quad: patches 4q..4q+3
    const int s = l >> 3;              // sub-row selector
    // f = 4w + s : float4 slot within patch slab; d = 4f + j
    const int srcoff = w * 512 + s * 4;

    const int a0 = __shfl_sync(0xffffffffu, pb, 4 * q + 0) + srcoff;
    const int a1 = __shfl_sync(0xffffffffu, pb, 4 * q + 1) + srcoff;
    const int a2 = __shfl_sync(0xffffffffu, pb, 4 * q + 2) + srcoff;
    const int a3 = __shfl_sync(0xffffffffu, pb, 4 * q + 3) + srcoff;

    // All 4 x loads in flight before any consumption (MLP 4)
    const float4 v0 = *reinterpret_cast<const float4*>(x + a0);
    const float4 v1 = *reinterpret_cast<const float4*>(x + a1);
    const float4 v2 = *reinterpret_cast<const float4*>(x + a2);
    const float4 v3 = *reinterpret_cast<const float4*>(x + a3);

    // Output rows 1 + d0 + 16w + 4s + j, cols p0 + 4q .. +3
    const int prow   = (1 + d0 + 16 * w + 4 * s) * 1024 + (p0 + 4 * q);
    const int outoff = out_b + prow;

    // 4 pos loads batched (L2-resident) before any store
    const float4 pe0 = *reinterpret_cast<const float4*>(pos + prow);
    const float4 pe1 = *reinterpret_cast<const float4*>(pos + prow + 1024);
    const float4 pe2 = *reinterpret_cast<const float4*>(pos + prow + 2048);
    const float4 pe3 = *reinterpret_cast<const float4*>(pos + prow + 3072);

    float4 r;
    r = make_float4(v0.x + pe0.x, v1.x + pe0.y, v2.x + pe0.z, v3.x + pe0.w);
    *reinterpret_cast<float4*>(out + outoff) = r;
    r = make_float4(v0.y + pe1.x, v1.y + pe1.y, v2.y + pe1.z, v3.y + pe1.w);
    *reinterpret_cast<float4*>(out + outoff + 1024) = r;
    r = make_float4(v0.z + pe2.x, v1.z + pe2.y, v2.z + pe2.z, v3.z + pe2.w);
    *reinterpret_cast<float4*>(out + outoff + 2048) = r;
    r = make_float4(v0.w + pe3.x, v1.w + pe3.y, v2.w + pe3.z, v3.w + pe3.w);
    *reinterpret_cast<float4*>(out + outoff + 3072) = r;
}

extern "C" void kernel_launch(void* const* d_in, const int* in_sizes, int n_in,
                              void* d_out, int out_size)
{
    // Identify inputs by size (defensive against ordering):
    //   x: 64*4*512*512 = 67108864, cls: 1024, pos: 1025*1024 = 1049600
    const float* x   = nullptr;
    const float* cls = nullptr;
    const float* pos = nullptr;
    for (int i = 0; i < n_in; i++) {
        if (in_sizes[i] == 67108864)     x   = (const float*)d_in[i];
        else if (in_sizes[i] == 1024)    cls = (const float*)d_in[i];
        else if (in_sizes[i] == 1049600) pos = (const float*)d_in[i];
    }
    float* out = (float*)d_out;

    dim3 grid(32, 8, 64);   // p-tiles, d-tiles, batch
    hilbert_main_kernel<<<grid, 256>>>(x, cls, pos, out);
}

// round 13
// speedup vs baseline: 1.0004x; 1.0004x over previous
#include <cuda_runtime.h>
#include <cuda_bf16.h>

// out[b, 1+d, p] = x[b, c, hx(p)*16+pi, hy(p)*16+pj] + pos[1+d, p]
//   where d = c*256 + pi*16 + pj, (hx,hy) = hilbert_d2xy(32, p)
// out[b, 0, e]   = cls[e] + pos[0, e]   (fused into ptile==0,dtile==0 CTA)
//
// FINAL (lock-in of the bench-best R5 form). Smem-free 4x4 register
// transpose: 8-lane groups read full 64B patch rows (full sectors, MLP-4
// batched), 4 pos loads (L2-resident) batched before stores, every STG.128
// writes a full 128B output line per 8-lane group. No smem, no barriers.
// Eight structural/scheduling variants (occupancy 32-92%, MLP 4-8, smem
// pipelines, pos amortization, raster order, store cache-ops) all converge
// at 6.2-6.34 TB/s: the compulsory-traffic memory wall (~87% of HBM spec
// at the pins for a 50/50 read/write stream).

__global__ __launch_bounds__(256) void hilbert_main_kernel(
    const float* __restrict__ x,
    const float* __restrict__ cls,
    const float* __restrict__ pos,
    float* __restrict__ out)
{
    const int tid = threadIdx.x;
    const int w   = tid >> 5;          // warp 0..7  -> d-quads 4w..4w+3
    const int l   = tid & 31;

    const int ptile = blockIdx.x;      // 0..31
    const int dtile = blockIdx.y;      // 0..7
    const int b     = blockIdx.z;      // 0..63

    const int c   = dtile >> 1;        // channel
    const int pi0 = (dtile & 1) * 8;   // starting patch row within channel
    const int p0  = ptile * 32;
    const int d0  = dtile * 128;
    const int out_b = b * (1025 * 1024);

    // Per-lane Hilbert d2xy for patch p0+l (N=32, 5 iterations)
    int pb;
    {
        int t = p0 + l;
        int hx = 0, hy = 0;
        #pragma unroll
        for (int s = 1; s < 32; s <<= 1) {
            int rx = 1 & (t >> 1);
            int ry = 1 & (t ^ rx);
            if (ry == 0) {
                if (rx == 1) { hx = s - 1 - hx; hy = s - 1 - hy; }
                int tmp = hx; hx = hy; hy = tmp;
            }
            hx += s * rx;
            hy += s * ry;
            t >>= 2;
        }
        pb = ((b * 4 + c) * 512 + hx * 16 + pi0) * 512 + hy * 16;
    }

    // Fused row0: out[b, 0, :] = cls + pos[0, :]  (one CTA per batch)
    if (ptile == 0 && dtile == 0) {
        float4 cv = *reinterpret_cast<const float4*>(cls + tid * 4);
        float4 pv = *reinterpret_cast<const float4*>(pos + tid * 4);
        cv.x += pv.x; cv.y += pv.y; cv.z += pv.z; cv.w += pv.w;
        *reinterpret_cast<float4*>(out + out_b + tid * 4) = cv;
    }

    const int q = l & 7;               // p-quad: patches 4q..4q+3
    const int s = l >> 3;              // sub-row selector
    // f = 4w + s : float4 slot within patch slab; d = 4f + j
    const int srcoff = w * 512 + s * 4;

    const int a0 = __shfl_sync(0xffffffffu, pb, 4 * q + 0) + srcoff;
    const int a1 = __shfl_sync(0xffffffffu, pb, 4 * q + 1) + srcoff;
    const int a2 = __shfl_sync(0xffffffffu, pb, 4 * q + 2) + srcoff;
    const int a3 = __shfl_sync(0xffffffffu, pb, 4 * q + 3) + srcoff;

    // All 4 x loads in flight before any consumption (MLP 4)
    const float4 v0 = *reinterpret_cast<const float4*>(x + a0);
    const float4 v1 = *reinterpret_cast<const float4*>(x + a1);
    const float4 v2 = *reinterpret_cast<const float4*>(x + a2);
    const float4 v3 = *reinterpret_cast<const float4*>(x + a3);

    // Output rows 1 + d0 + 16w + 4s + j, cols p0 + 4q .. +3
    const int prow   = (1 + d0 + 16 * w + 4 * s) * 1024 + (p0 + 4 * q);
    const int outoff = out_b + prow;

    // 4 pos loads batched (L2-resident) before any store
    const float4 pe0 = *reinterpret_cast<const float4*>(pos + prow);
    const float4 pe1 = *reinterpret_cast<const float4*>(pos + prow + 1024);
    const float4 pe2 = *reinterpret_cast<const float4*>(pos + prow + 2048);
    const float4 pe3 = *reinterpret_cast<const float4*>(pos + prow + 3072);

    float4 r;
    r = make_float4(v0.x + pe0.x, v1.x + pe0.y, v2.x + pe0.z, v3.x + pe0.w);
    __stcs(reinterpret_cast<float4*>(out + outoff), r);
    r = make_float4(v0.y + pe1.x, v1.y + pe1.y, v2.y + pe1.z, v3.y + pe1.w);
    __stcs(reinterpret_cast<float4*>(out + outoff + 1024), r);
    r = make_float4(v0.z + pe2.x, v1.z + pe2.y, v2.z + pe2.z, v3.z + pe2.w);
    __stcs(reinterpret_cast<float4*>(out + outoff + 2048), r);
    r = make_float4(v0.w + pe3.x, v1.w + pe3.y, v2.w + pe3.z, v3.w + pe3.w);
    __stcs(reinterpret_cast<float4*>(out + outoff + 3072), r);
}

extern "C" void kernel_launch(void* const* d_in, const int* in_sizes, int n_in,
                              void* d_out, int out_size)
{
    // Identify inputs by size (defensive against ordering):
    //   x: 64*4*512*512 = 67108864, cls: 1024, pos: 1025*1024 = 1049600
    const float* x   = nullptr;
    const float* cls = nullptr;
    const float* pos = nullptr;
    for (int i = 0; i < n_in; i++) {
        if (in_sizes[i] == 67108864)     x   = (const float*)d_in[i];
        else if (in_sizes[i] == 1024)    cls = (const float*)d_in[i];
        else if (in_sizes[i] == 1049600) pos = (const float*)d_in[i];
    }
    float* out = (float*)d_out;

    dim3 grid(32, 8, 64);   // p-tiles, d-tiles, batch
    hilbert_main_kernel<<<grid, 256>>>(x, cls, pos, out);
}

// round 14
// speedup vs baseline: 1.0055x; 1.0051x over previous
#include <cuda_runtime.h>
#include <cuda_bf16.h>

// out[b, 1+d, p] = x[b, c, hx(p)*16+pi, hy(p)*16+pj] + pos[1+d, p]
//   where d = c*256 + pi*16 + pj, (hx,hy) = hilbert_d2xy(32, p)
// out[b, 0, e]   = cls[e] + pos[0, e]   (fused into ptile==0,dtile==0 CTA)
//
// FINAL. Smem-free 4x4 register transpose: 8-lane groups read full 64B
// patch rows (full sectors, MLP-4 batched), 4 pos loads (L2-resident)
// batched before stores, every STG.128 writes a full 128B output line per
// 8-lane group. No smem, no barriers.
//
// Nine structural/scheduling variants (occupancy 32-92%, MLP 4-8, smem
// pipelines, pos amortization, raster order, store cache-ops, addressing)
// all converge at 6.2-6.34 TB/s ncu DRAM: 537 MB compulsory traffic in
// ~77 us = ~6.97 TB/s at the pins (~87% of HBM spec) for a 50/50
// read/write stream. Cross-checks (R8: low L1/issue, same DRAM; R9: 32%
// occ, best DRAM) rule out every non-DRAM binder. This is the roofline.

__global__ __launch_bounds__(256) void hilbert_main_kernel(
    const float* __restrict__ x,
    const float* __restrict__ cls,
    const float* __restrict__ pos,
    float* __restrict__ out)
{
    const int tid = threadIdx.x;
    const int w   = tid >> 5;          // warp 0..7  -> d-quads 4w..4w+3
    const int l   = tid & 31;

    const int ptile = blockIdx.x;      // 0..31
    const int dtile = blockIdx.y;      // 0..7
    const int b     = blockIdx.z;      // 0..63

    const int c   = dtile >> 1;        // channel
    const int pi0 = (dtile & 1) * 8;   // starting patch row within channel
    const int p0  = ptile * 32;
    const int d0  = dtile * 128;
    const int out_b = b * (1025 * 1024);

    // Per-lane Hilbert d2xy for patch p0+l (N=32, 5 iterations)
    int pb;
    {
        int t = p0 + l;
        int hx = 0, hy = 0;
        #pragma unroll
        for (int s = 1; s < 32; s <<= 1) {
            int rx = 1 & (t >> 1);
            int ry = 1 & (t ^ rx);
            if (ry == 0) {
                if (rx == 1) { hx = s - 1 - hx; hy = s - 1 - hy; }
                int tmp = hx; hx = hy; hy = tmp;
            }
            hx += s * rx;
            hy += s * ry;
            t >>= 2;
        }
        pb = ((b * 4 + c) * 512 + hx * 16 + pi0) * 512 + hy * 16;
    }

    // Fused row0: out[b, 0, :] = cls + pos[0, :]  (one CTA per batch)
    if (ptile == 0 && dtile == 0) {
        float4 cv = *reinterpret_cast<const float4*>(cls + tid * 4);
        float4 pv = *reinterpret_cast<const float4*>(pos + tid * 4);
        cv.x += pv.x; cv.y += pv.y; cv.z += pv.z; cv.w += pv.w;
        *reinterpret_cast<float4*>(out + out_b + tid * 4) = cv;
    }

    const int q = l & 7;               // p-quad: patches 4q..4q+3
    const int s = l >> 3;              // sub-row selector
    // f = 4w + s : float4 slot within patch slab; d = 4f + j
    const int srcoff = w * 512 + s * 4;

    const int a0 = __shfl_sync(0xffffffffu, pb, 4 * q + 0) + srcoff;
    const int a1 = __shfl_sync(0xffffffffu, pb, 4 * q + 1) + srcoff;
    const int a2 = __shfl_sync(0xffffffffu, pb, 4 * q + 2) + srcoff;
    const int a3 = __shfl_sync(0xffffffffu, pb, 4 * q + 3) + srcoff;

    // All 4 x loads in flight before any consumption (MLP 4)
    const float4 v0 = *reinterpret_cast<const float4*>(x + a0);
    const float4 v1 = *reinterpret_cast<const float4*>(x + a1);
    const float4 v2 = *reinterpret_cast<const float4*>(x + a2);
    const float4 v3 = *reinterpret_cast<const float4*>(x + a3);

    // Output rows 1 + d0 + 16w + 4s + j, cols p0 + 4q .. +3
    const int prow   = (1 + d0 + 16 * w + 4 * s) * 1024 + (p0 + 4 * q);
    const int outoff = out_b + prow;

    // 4 pos loads batched (L2-resident) before any store
    const float4 pe0 = *reinterpret_cast<const float4*>(pos + prow);
    const float4 pe1 = *reinterpret_cast<const float4*>(pos + prow + 1024);
    const float4 pe2 = *reinterpret_cast<const float4*>(pos + prow + 2048);
    const float4 pe3 = *reinterpret_cast<const float4*>(pos + prow + 3072);

    float4 r;
    r = make_float4(v0.x + pe0.x, v1.x + pe0.y, v2.x + pe0.z, v3.x + pe0.w);
    __stcs(reinterpret_cast<float4*>(out + outoff), r);
    r = make_float4(v0.y + pe1.x, v1.y + pe1.y, v2.y + pe1.z, v3.y + pe1.w);
    __stcs(reinterpret_cast<float4*>(out + outoff + 1024), r);
    r = make_float4(v0.z + pe2.x, v1.z + pe2.y, v2.z + pe2.z, v3.z + pe2.w);
    __stcs(reinterpret_cast<float4*>(out + outoff + 2048), r);
    r = make_float4(v0.w + pe3.x, v1.w + pe3.y, v2.w + pe3.z, v3.w + pe3.w);
    __stcs(reinterpret_cast<float4*>(out + outoff + 3072), r);
}

extern "C" void kernel_launch(void* const* d_in, const int* in_sizes, int n_in,
                              void* d_out, int out_size)
{
    // Identify inputs by size (defensive against ordering):
    //   x: 64*4*512*512 = 67108864, cls: 1024, pos: 1025*1024 = 1049600
    const float* x   = nullptr;
    const float* cls = nullptr;
    const float* pos = nullptr;
    for (int i = 0; i < n_in; i++) {
        if (in_sizes[i] == 67108864)     x   = (const float*)d_in[i];
        else if (in_sizes[i] == 1024)    cls = (const float*)d_in[i];
        else if (in_sizes[i] == 1049600) pos = (const float*)d_in[i];
    }
    float* out = (float*)d_out;

    dim3 grid(32, 8, 64);   // p-tiles, d-tiles, batch
    hilbert_main_kernel<<<grid, 256>>>(x, cls, pos, out);
}